// round 14
// baseline (speedup 1.0000x reference)
#include <cuda_runtime.h>
#include <cuda_fp16.h>
#include <math.h>
#include <stdint.h>

#define B_TOK 65536
#define D_DIM 4096
#define E_EXP 64
#define K_TOP 8

#define TM   128
#define NBLK (B_TOK / TM)        // 512 CTAs
#define KC   64
#define NCH  (D_DIM / KC)        // 64 chunks
#define NCOL 128
#define GAP_THETA 6e-3f
#define SPLITK   16
#define KPS      (NCH / SPLITK)  // 4 chunks per slice
#define MAXTILES 64              // flag capacity = 8192 rows
#define CAPROWS  (MAXTILES * TM)

__device__ __half g_wh[NCOL * D_DIM];
__device__ __half g_wl[NCOL * D_DIM];
__device__ double g_ps[NBLK];
__device__ double g_sq[NBLK];
__device__ int    g_nflag;
__device__ int    g_flagrows[CAPROWS];
__device__ float  g_scratch[(size_t)SPLITK * MAXTILES * TM * NCOL];   // 67 MB

// main: X hi 0..16K | W hi buf b: 16384 + b*16384            (48KB)
// repair A: XH 0..16K, XL 16K..32K | W buf b: 32768 + b*32768
// epilogue overlay: LG 0 float[128][129] | NSRS 66048 float[128][65]
#define XB_OFF 0
#define XL_OFF 16384
#define WBM_OFF(b) (16384 + (b) * 16384)
#define WBR_OFF(b) (32768 + (b) * 32768)
#define LG_OFF 0
#define NS_OFF 66048
#define SMEM_BYTES (66048 + 33280)   // 99328

static __device__ __forceinline__ uint32_t smem_u32(const void* p) {
    uint32_t a;
    asm("{ .reg .u64 t; cvta.to.shared.u64 t, %1; cvt.u32.u64 %0, t; }" : "=r"(a) : "l"(p));
    return a;
}
static __device__ __forceinline__ uint32_t sw128(uint32_t off) { return off ^ ((off >> 3) & 0x70); }
static __device__ __forceinline__ uint32_t pkh(__half a, __half b) {
    return (uint32_t)__half_as_ushort(a) | ((uint32_t)__half_as_ushort(b) << 16);
}

#define LDSM4(r, a) \
    asm volatile("ldmatrix.sync.aligned.m8n8.x4.shared.b16 {%0,%1,%2,%3}, [%4];" \
        : "=r"((r)[0]), "=r"((r)[1]), "=r"((r)[2]), "=r"((r)[3]) : "r"(a))

static __device__ __forceinline__ void mma16816(float* d, const uint32_t* a, uint32_t b0, uint32_t b1) {
    asm volatile("mma.sync.aligned.m16n8k16.row.col.f32.f16.f16.f32 "
        "{%0,%1,%2,%3}, {%4,%5,%6,%7}, {%8,%9}, {%0,%1,%2,%3};"
        : "+f"(d[0]), "+f"(d[1]), "+f"(d[2]), "+f"(d[3])
        : "r"(a[0]), "r"(a[1]), "r"(a[2]), "r"(a[3]), "r"(b0), "r"(b1));
}

#define CP_ASYNC16(dst, src) asm volatile("cp.async.cg.shared.global [%0], [%1], 16;" :: "r"(dst), "l"(src) : "memory")
#define CP_COMMIT()          asm volatile("cp.async.commit_group;" ::: "memory")
#define CP_WAIT1()           asm volatile("cp.async.wait_group 1;" ::: "memory")
#define CP_WAIT0()           asm volatile("cp.async.wait_group 0;" ::: "memory")

__global__ void reset_kernel() { if (threadIdx.x == 0) g_nflag = 0; }

__global__ void wconv_kernel(const float* __restrict__ wg, const float* __restrict__ wn)
{
    int idx = blockIdx.x * 256 + threadIdx.x;
    if (idx >= D_DIM * E_EXP) return;
    int k = idx >> 6, n = idx & 63;
    float f = wg[idx] * 64.f;
    __half h = __float2half(f);
    g_wh[(size_t)n * D_DIM + k] = h;
    g_wl[(size_t)n * D_DIM + k] = __float2half(f - __half2float(h));
    f = wn[idx] * 64.f;
    h = __float2half(f);
    g_wh[(size_t)(64 + n) * D_DIM + k] = h;
    g_wl[(size_t)(64 + n) * D_DIM + k] = __float2half(f - __half2float(h));
}

// main: 1024 uint4 per chunk (hi only); 256 threads -> 4 each
static __device__ __forceinline__ void issue_w_main(uint32_t base, int t, int k0) {
#pragma unroll
    for (int i = 0; i < 4; i++) {
        int idx = t + (i << 8);                 // 0..1023
        int n = idx >> 3, q = idx & 7;
        const __half* src = g_wh + (size_t)n * D_DIM + k0 + (q << 3);
        uint32_t dst = base + sw128((n << 7) + (q << 4));
        CP_ASYNC16(dst, src);
    }
}
// repair: 2048 uint4 per chunk (hi + lo)
static __device__ __forceinline__ void issue_w_rep(uint32_t base, int t, int k0) {
#pragma unroll
    for (int i = 0; i < 8; i++) {
        int idx = t + (i << 8);
        int v   = idx >> 10;
        int rem = idx & 1023;
        int n = rem >> 3, q = rem & 7;
        const __half* src = (v ? g_wl : g_wh) + (size_t)n * D_DIM + k0 + (q << 3);
        uint32_t dst = base + (v << 14) + sw128((n << 7) + (q << 4));
        CP_ASYNC16(dst, src);
    }
}

static __device__ __forceinline__ void row_gate(float* lgrow, const float* nsrow,
                                                float* rsrow, float* v8o, float* v9o)
{
    float m = -INFINITY;
    for (int e = 0; e < E_EXP; ++e) {
        float cl = lgrow[e]      * 0.015625f;
        float nr = lgrow[64 + e] * 0.015625f;
        float sd = (nr > 20.f) ? nr : log1pf(__expf(nr));
        float v  = cl + nsrow[e] * sd;
        lgrow[e] = v;
        m = fmaxf(m, v);
    }
    unsigned long long sel = 0ULL;
    float m8 = 0.f, v8 = 0.f;
    for (int kk = 0; kk < K_TOP; ++kk) {
        float best = -INFINITY; int bi = 0;
        for (int e = 0; e < E_EXP; ++e) {
            if (!((sel >> e) & 1ULL)) {
                float v = lgrow[e];
                if (v > best) { best = v; bi = e; }
            }
        }
        sel |= 1ULL << bi;
        if (kk == 0) m8 = best;
        if (kk == K_TOP - 1) v8 = best;
    }
    float v9 = -INFINITY;
    for (int e = 0; e < E_EXP; ++e)
        if (!((sel >> e) & 1ULL)) v9 = fmaxf(v9, lgrow[e]);
    float s8 = 0.f;
    for (int e = 0; e < E_EXP; ++e)
        if ((sel >> e) & 1ULL) s8 += __expf(lgrow[e] - m8);
    float inv8 = 1.f / s8;
    for (int e = 0; e < E_EXP; ++e)
        rsrow[e] = ((sel >> e) & 1ULL) ? __expf(lgrow[e] - m8) * inv8 : 0.f;
    *v8o = v8; *v9o = v9;
}

__global__ __launch_bounds__(256, 2)
void gate_mma_kernel(const float* __restrict__ x,
                     const float* __restrict__ noise,
                     float* __restrict__ out, int out_elems)
{
    extern __shared__ char smem[];
    const uint32_t sb = smem_u32(smem);
    const int t   = threadIdx.x;
    const int wid = t >> 5;
    const int lid = t & 31;
    const int wm  = wid & 1;
    const int wn  = wid >> 1;
    const int row0 = blockIdx.x * TM;
    const float* xp = x + (size_t)row0 * D_DIM;

    float acc[4][4][4];
#pragma unroll
    for (int a = 0; a < 4; a++)
#pragma unroll
        for (int b = 0; b < 4; b++)
#pragma unroll
            for (int c = 0; c < 4; c++) acc[a][b][c] = 0.f;

    const uint32_t xmask     = (uint32_t)(lid & 7) << 4;
    const uint32_t a_rowbase = (uint32_t)(wm * 64 + ((lid >> 3) & 1) * 8 + (lid & 7)) * 128;
    const uint32_t a_kincr   = (uint32_t)(lid >> 4) * 16;
    const uint32_t b_rowbase = (uint32_t)(wn * 32 + ((lid >> 4) << 3) + (lid & 7)) * 128;
    const uint32_t b_kincr   = (uint32_t)((lid >> 3) & 1) * 16;

    const int xr_ = t >> 4;
    const int xj_ = t & 15;

    auto store_x = [&](const float4* v) {
#pragma unroll
        for (int i = 0; i < 8; ++i) {
            int r = xr_ + (i << 4);
            uint32_t sw = sw128((r << 7) + (xj_ << 3));
            *(uint2*)(smem + XB_OFF + sw) =
                make_uint2(pkh(__float2half(v[i].x), __float2half(v[i].y)),
                           pkh(__float2half(v[i].z), __float2half(v[i].w)));
        }
    };

    // ---- prologue: w(0) in flight; x(0) -> regs -> XB ----
    issue_w_main(sb + WBM_OFF(0), t, 0); CP_COMMIT();
    {
        float4 v[8];
#pragma unroll
        for (int i = 0; i < 8; ++i)
            v[i] = *(const float4*)(xp + (size_t)(xr_ + (i << 4)) * D_DIM + (xj_ << 2));
        store_x(v);
    }
    CP_WAIT0();
    __syncthreads();

    for (int c = 0; c < NCH; ++c) {
        // w(c+1) into the other buffer (reader MMA(c-1) drained by last sync)
        if (c + 1 < NCH) { issue_w_main(sb + WBM_OFF((c + 1) & 1), t, (c + 1) * KC); CP_COMMIT(); }

        // LDG next x into regs — DRAM latency hides under MMA(c)
        float4 v[8];
        if (c + 1 < NCH) {
            const int k0n = (c + 1) * KC;
#pragma unroll
            for (int i = 0; i < 8; ++i)
                v[i] = *(const float4*)(xp + (size_t)(xr_ + (i << 4)) * D_DIM + k0n + (xj_ << 2));
        }

        // ---- MMA(c) on XB, WBM(c&1) ----
        const uint32_t wb = sb + WBM_OFF(c & 1);
#pragma unroll
        for (int ks = 0; ks < 4; ++ks) {
            const uint32_t boff = (uint32_t)(ks * 32 + b_kincr) ^ xmask;
            uint32_t bH[8];
            LDSM4(&bH[0], wb + b_rowbase + boff);
            LDSM4(&bH[4], wb + b_rowbase + 2048 + boff);
            const uint32_t aoff = (uint32_t)(ks * 32 + a_kincr) ^ xmask;
#pragma unroll
            for (int mt = 0; mt < 4; ++mt) {
                uint32_t aH[4];
                LDSM4(aH, sb + XB_OFF + a_rowbase + mt * 2048 + aoff);
#pragma unroll
                for (int nt = 0; nt < 4; ++nt) {
                    int bi = (nt >> 1) * 4 + (nt & 1) * 2;
                    mma16816(acc[mt][nt], aH, bH[bi], bH[bi + 1]);
                }
            }
        }

        __syncthreads();                 // all MMA reads of XB done
        if (c + 1 < NCH) {
            store_x(v);                  // only cvt+STS exposed
            CP_WAIT0();                  // w(c+1) landed
            __syncthreads();
        }
    }

    // ================= epilogue =================
    __syncthreads();
    float* lg   = (float*)(smem + LG_OFF);
    float* nsrs = (float*)(smem + NS_OFF);

#pragma unroll
    for (int i = 0; i < 32; i++) {
        int idx = t + (i << 8);
        nsrs[(idx >> 6) * 65 + (idx & 63)] = noise[(size_t)row0 * E_EXP + idx];
    }
#pragma unroll
    for (int mt = 0; mt < 4; ++mt) {
        int r = wm * 64 + mt * 16 + (lid >> 2);
#pragma unroll
        for (int nt = 0; nt < 4; ++nt) {
            int c0 = wn * 32 + nt * 8 + (lid & 3) * 2;
            lg[r * 129 + c0]           = acc[mt][nt][0];
            lg[r * 129 + c0 + 1]       = acc[mt][nt][1];
            lg[(r + 8) * 129 + c0]     = acc[mt][nt][2];
            lg[(r + 8) * 129 + c0 + 1] = acc[mt][nt][3];
        }
    }
    __syncthreads();

    double ps_d = 0.0, sq_d = 0.0;
    if (t < TM) {
        const int r = t;
        float v8, v9;
        row_gate(lg + r * 129, nsrs + r * 65, nsrs + r * 65, &v8, &v9);
        float m = -INFINITY;
        for (int e = 0; e < E_EXP; ++e) m = fmaxf(m, lg[r * 129 + e]);
        float s = 0.f;
        for (int e = 0; e < E_EXP; ++e) s += __expf(lg[r * 129 + e] - m);
        float inv = 1.f / s;
        float ps = 0.f, sq = 0.f;
        for (int e = 0; e < E_EXP; ++e) {
            float p = __expf(lg[r * 129 + e] - m) * inv;
            ps += p; sq += p * p;
        }
        ps_d = ps; sq_d = sq;
        if (v8 - v9 < GAP_THETA) {
            int i = atomicAdd(&g_nflag, 1);
            if (i < CAPROWS) g_flagrows[i] = row0 + r;
        }
    }

    __shared__ double wps[4], wsq[4];
#pragma unroll
    for (int o = 16; o > 0; o >>= 1) {
        ps_d += __shfl_down_sync(0xffffffffu, ps_d, o);
        sq_d += __shfl_down_sync(0xffffffffu, sq_d, o);
    }
    if (wid < 4 && lid == 0) { wps[wid] = ps_d; wsq[wid] = sq_d; }
    __syncthreads();
    if (t == 0) {
        g_ps[blockIdx.x] = wps[0] + wps[1] + wps[2] + wps[3];
        g_sq[blockIdx.x] = wsq[0] + wsq[1] + wsq[2] + wsq[3];
    }
#pragma unroll
    for (int i = 0; i < 32; i++) {
        int idx = t + (i << 8);
        size_t o = (size_t)row0 * E_EXP + idx;
        if (o < (size_t)out_elems) out[o] = nsrs[(idx >> 6) * 65 + (idx & 63)];
    }
}

// ---- Phase A: split-K 4-product repair GEMM, partials -> scratch ----
__global__ __launch_bounds__(256, 2)
void repair_gemm_kernel(const float* __restrict__ x)
{
    extern __shared__ char smem[];
    const uint32_t sb = smem_u32(smem);
    const int t   = threadIdx.x;
    const int wid = t >> 5;
    const int lid = t & 31;
    const int wm  = wid & 1;
    const int wn  = wid >> 1;

    const int nf = min(g_nflag, CAPROWS);
    const int ntiles = (nf + TM - 1) / TM;
    const int nitems = ntiles * SPLITK;

    __shared__ int ridx[TM];

    const uint32_t xmask     = (uint32_t)(lid & 7) << 4;
    const uint32_t a_rowbase = (uint32_t)(wm * 64 + ((lid >> 3) & 1) * 8 + (lid & 7)) * 128;
    const uint32_t a_kincr   = (uint32_t)(lid >> 4) * 16;
    const uint32_t b_rowbase = (uint32_t)(wn * 32 + ((lid >> 4) << 3) + (lid & 7)) * 128;
    const uint32_t b_kincr   = (uint32_t)((lid >> 3) & 1) * 16;
    const int xr_ = t >> 4;
    const int xj_ = t & 15;

    for (int item = blockIdx.x; item < nitems; item += gridDim.x) {
        const int tile  = item >> 4;
        const int slice = item & (SPLITK - 1);
        const int kbase = slice * KPS * KC;

        __syncthreads();
        if (t < TM) {
            int gi = tile * TM + t;
            ridx[t] = g_flagrows[gi < nf ? gi : nf - 1];
        }
        issue_w_rep(sb + WBR_OFF(0), t, kbase); CP_COMMIT();
        __syncthreads();

        float acc[4][4][4];
#pragma unroll
        for (int a = 0; a < 4; a++)
#pragma unroll
            for (int b = 0; b < 4; b++)
#pragma unroll
                for (int c = 0; c < 4; c++) acc[a][b][c] = 0.f;

        for (int j = 0; j < KPS; ++j) {
            const int k0 = kbase + j * KC;
            if (j) __syncthreads();
#pragma unroll
            for (int i = 0; i < 8; ++i) {
                int r = xr_ + (i << 4);
                float4 v = *(const float4*)(x + (size_t)ridx[r] * D_DIM + k0 + (xj_ << 2));
                __half h0 = __float2half(v.x), h1 = __float2half(v.y);
                __half h2 = __float2half(v.z), h3 = __float2half(v.w);
                __half l0 = __float2half(v.x - __half2float(h0)), l1 = __float2half(v.y - __half2float(h1));
                __half l2 = __float2half(v.z - __half2float(h2)), l3 = __float2half(v.w - __half2float(h3));
                uint32_t sw = sw128((r << 7) + (xj_ << 3));
                *(uint2*)(smem + XB_OFF + sw) = make_uint2(pkh(h0, h1), pkh(h2, h3));
                *(uint2*)(smem + XL_OFF + sw) = make_uint2(pkh(l0, l1), pkh(l2, l3));
            }
            if (j < KPS - 1) { issue_w_rep(sb + WBR_OFF((j + 1) & 1), t, k0 + KC); CP_COMMIT(); CP_WAIT1(); }
            else             { CP_WAIT0(); }
            __syncthreads();

            const uint32_t wb = sb + WBR_OFF(j & 1);
#pragma unroll
            for (int ks = 0; ks < 4; ++ks) {
                const uint32_t boff = (uint32_t)(ks * 32 + b_kincr) ^ xmask;
                uint32_t bH[8], bL[8];
                LDSM4(&bH[0], wb + b_rowbase + boff);
                LDSM4(&bH[4], wb + b_rowbase + 2048 + boff);
                LDSM4(&bL[0], wb + 16384 + b_rowbase + boff);
                LDSM4(&bL[4], wb + 16384 + b_rowbase + 2048 + boff);
                const uint32_t aoff = (uint32_t)(ks * 32 + a_kincr) ^ xmask;
#pragma unroll
                for (int mt = 0; mt < 4; ++mt) {
                    uint32_t aH[4], aL[4];
                    LDSM4(aH, sb + XB_OFF + a_rowbase + mt * 2048 + aoff);
                    LDSM4(aL, sb + XL_OFF + a_rowbase + mt * 2048 + aoff);
#pragma unroll
                    for (int nt = 0; nt < 4; ++nt) {
                        int bi = (nt >> 1) * 4 + (nt & 1) * 2;
                        mma16816(acc[mt][nt], aH, bH[bi], bH[bi + 1]);
                        mma16816(acc[mt][nt], aH, bL[bi], bL[bi + 1]);
                        mma16816(acc[mt][nt], aL, bH[bi], bH[bi + 1]);
                        mma16816(acc[mt][nt], aL, bL[bi], bL[bi + 1]);
                    }
                }
            }
        }

        float* dst = g_scratch + ((size_t)slice * MAXTILES + tile) * (TM * NCOL);
#pragma unroll
        for (int mt = 0; mt < 4; ++mt) {
            int r = wm * 64 + mt * 16 + (lid >> 2);
#pragma unroll
            for (int nt = 0; nt < 4; ++nt) {
                int c0 = wn * 32 + nt * 8 + (lid & 3) * 2;
                dst[r * NCOL + c0]           = acc[mt][nt][0];
                dst[r * NCOL + c0 + 1]       = acc[mt][nt][1];
                dst[(r + 8) * NCOL + c0]     = acc[mt][nt][2];
                dst[(r + 8) * NCOL + c0 + 1] = acc[mt][nt][3];
            }
        }
    }
}

// ---- Phase B: deterministic slice-sum + row_gate + scatter ----
__global__ __launch_bounds__(256, 2)
void repair_fix_kernel(const float* __restrict__ noise, float* __restrict__ out)
{
    extern __shared__ char smem[];
    float* lg   = (float*)(smem + LG_OFF);
    float* nsrs = (float*)(smem + NS_OFF);
    const int t = threadIdx.x;
    const int nf = min(g_nflag, CAPROWS);
    const int ntiles = (nf + TM - 1) / TM;

    for (int tile = blockIdx.x; tile < ntiles; tile += gridDim.x) {
        __syncthreads();
        for (int idx = t; idx < TM * NCOL; idx += 256) {
            int r = idx >> 7, c = idx & 127;
            float s = 0.f;
            const float* src = g_scratch + (size_t)tile * (TM * NCOL) + idx;
#pragma unroll
            for (int sl = 0; sl < SPLITK; ++sl)
                s += src[(size_t)sl * MAXTILES * TM * NCOL];
            lg[r * 129 + c] = s;
        }
        if (t < TM) {
            int gi = tile * TM + t;
            if (gi < nf) {
                const float* nrow = noise + (size_t)g_flagrows[gi] * E_EXP;
                for (int e = 0; e < E_EXP; ++e) nsrs[t * 65 + e] = nrow[e];
            }
        }
        __syncthreads();
        if (t < TM) {
            int gi = tile * TM + t;
            if (gi < nf) {
                float v8, v9;
                row_gate(lg + t * 129, nsrs + t * 65, nsrs + t * 65, &v8, &v9);
                float* orow = out + (size_t)g_flagrows[gi] * E_EXP;
                for (int e = 0; e < E_EXP; ++e) orow[e] = nsrs[t * 65 + e];
            }
        }
    }
}

__global__ void finalize_kernel(float* __restrict__ out, int out_elems)
{
    __shared__ double ssum[256], ssq[256];
    double a = 0.0, b = 0.0;
    for (int i = threadIdx.x; i < NBLK; i += 256) { a += g_ps[i]; b += g_sq[i]; }
    ssum[threadIdx.x] = a; ssq[threadIdx.x] = b;
    __syncthreads();
    for (int s = 128; s > 0; s >>= 1) {
        if (threadIdx.x < s) {
            ssum[threadIdx.x] += ssum[threadIdx.x + s];
            ssq[threadIdx.x]  += ssq[threadIdx.x + s];
        }
        __syncthreads();
    }
    if (threadIdx.x == 0) {
        double n    = (double)B_TOK * (double)E_EXP;
        double mean = ssum[0] / n;
        double var  = (ssq[0] - n * mean * mean) / (n - 1.0);
        float loss  = (float)(var / (mean * mean + 1e-10));
        long long base = (long long)B_TOK * E_EXP;
        if (out_elems == 1) out[0] = loss;
        else for (long long i = base; i < (long long)out_elems; i++) out[i] = loss;
    }
}

extern "C" void kernel_launch(void* const* d_in, const int* in_sizes, int n_in,
                              void* d_out, int out_size)
{
    const float* x  = (const float*)d_in[0];
    const float* wg = (const float*)d_in[1];
    const float* wn = (const float*)d_in[2];
    const float* nz = (const float*)d_in[3];
    float* out = (float*)d_out;

    cudaFuncSetAttribute(gate_mma_kernel,    cudaFuncAttributeMaxDynamicSharedMemorySize, SMEM_BYTES);
    cudaFuncSetAttribute(repair_gemm_kernel, cudaFuncAttributeMaxDynamicSharedMemorySize, SMEM_BYTES);
    cudaFuncSetAttribute(repair_fix_kernel,  cudaFuncAttributeMaxDynamicSharedMemorySize, SMEM_BYTES);

    reset_kernel<<<1, 32>>>();
    wconv_kernel<<<(D_DIM * E_EXP + 255) / 256, 256>>>(wg, wn);
    gate_mma_kernel<<<NBLK, 256, SMEM_BYTES>>>(x, nz, out, out_size);
    repair_gemm_kernel<<<NBLK, 256, SMEM_BYTES>>>(x);
    repair_fix_kernel<<<64, 256, SMEM_BYTES>>>(nz, out);
    finalize_kernel<<<1, 256>>>(out, out_size);
}

// round 15
// speedup vs baseline: 1.1800x; 1.1800x over previous
#include <cuda_runtime.h>
#include <cuda_fp16.h>
#include <math.h>
#include <stdint.h>

#define B_TOK 65536
#define D_DIM 4096
#define E_EXP 64
#define K_TOP 8

#define TM   128
#define NBLK (B_TOK / TM)        // 512 CTAs
#define KC   128                 // K per main chunk: two 128B SW128 planes
#define NCH  (D_DIM / KC)        // 32 chunks
#define KCR  64                  // repair chunk (unchanged)
#define NCHR (D_DIM / KCR)       // 64
#define NCOL 128
#define GAP_THETA 6e-3f
#define SPLITK   16
#define KPS      (NCHR / SPLITK) // 4 repair chunks per slice
#define MAXTILES 64
#define CAPROWS  (MAXTILES * TM)

__device__ __half g_wh[NCOL * D_DIM];
__device__ __half g_wl[NCOL * D_DIM];
__device__ double g_ps[NBLK];
__device__ double g_sq[NBLK];
__device__ int    g_nflag;
__device__ int    g_flagrows[CAPROWS];
__device__ float  g_scratch[(size_t)SPLITK * MAXTILES * TM * NCOL];

// main: X planes 0,16K | W buf b at 32768+b*32768, planes +0,+16K   (96KB)
// repair: XH 0..16K, XL 16K..32K | W buf b: 32768 + b*32768
// epilogue overlay: LG 0 float[128][129] | NSRS 66048 float[128][65]
#define XP_OFF(p)    ((p) * 16384)
#define WM_OFF(b,p)  (32768 + (b) * 32768 + (p) * 16384)
#define XL_OFF 16384
#define WBR_OFF(b)   (32768 + (b) * 32768)
#define LG_OFF 0
#define NS_OFF 66048
#define SMEM_BYTES (66048 + 33280)   // 99328

static __device__ __forceinline__ uint32_t smem_u32(const void* p) {
    uint32_t a;
    asm("{ .reg .u64 t; cvta.to.shared.u64 t, %1; cvt.u32.u64 %0, t; }" : "=r"(a) : "l"(p));
    return a;
}
static __device__ __forceinline__ uint32_t sw128(uint32_t off) { return off ^ ((off >> 3) & 0x70); }
static __device__ __forceinline__ uint32_t pkh(__half a, __half b) {
    return (uint32_t)__half_as_ushort(a) | ((uint32_t)__half_as_ushort(b) << 16);
}

#define LDSM4(r, a) \
    asm volatile("ldmatrix.sync.aligned.m8n8.x4.shared.b16 {%0,%1,%2,%3}, [%4];" \
        : "=r"((r)[0]), "=r"((r)[1]), "=r"((r)[2]), "=r"((r)[3]) : "r"(a))

static __device__ __forceinline__ void mma16816(float* d, const uint32_t* a, uint32_t b0, uint32_t b1) {
    asm volatile("mma.sync.aligned.m16n8k16.row.col.f32.f16.f16.f32 "
        "{%0,%1,%2,%3}, {%4,%5,%6,%7}, {%8,%9}, {%0,%1,%2,%3};"
        : "+f"(d[0]), "+f"(d[1]), "+f"(d[2]), "+f"(d[3])
        : "r"(a[0]), "r"(a[1]), "r"(a[2]), "r"(a[3]), "r"(b0), "r"(b1));
}

#define CP_ASYNC16(dst, src) asm volatile("cp.async.cg.shared.global [%0], [%1], 16;" :: "r"(dst), "l"(src) : "memory")
#define CP_COMMIT()          asm volatile("cp.async.commit_group;" ::: "memory")
#define CP_WAIT1()           asm volatile("cp.async.wait_group 1;" ::: "memory")
#define CP_WAIT0()           asm volatile("cp.async.wait_group 0;" ::: "memory")

__global__ void reset_kernel() { if (threadIdx.x == 0) g_nflag = 0; }

__global__ void wconv_kernel(const float* __restrict__ wg, const float* __restrict__ wn)
{
    int idx = blockIdx.x * 256 + threadIdx.x;
    if (idx >= D_DIM * E_EXP) return;
    int k = idx >> 6, n = idx & 63;
    float f = wg[idx] * 64.f;
    __half h = __float2half(f);
    g_wh[(size_t)n * D_DIM + k] = h;
    g_wl[(size_t)n * D_DIM + k] = __float2half(f - __half2float(h));
    f = wn[idx] * 64.f;
    h = __float2half(f);
    g_wh[(size_t)(64 + n) * D_DIM + k] = h;
    g_wl[(size_t)(64 + n) * D_DIM + k] = __float2half(f - __half2float(h));
}

// main chunk (KC=128, hi only): 2048 uint4 (2 planes x 1024); 256 thr -> 8 each
static __device__ __forceinline__ void issue_w_main(uint32_t sb, int buf, int t, int k0) {
#pragma unroll
    for (int i = 0; i < 8; i++) {
        int idx = t + (i << 8);                 // 0..2047
        int p   = idx >> 10;                    // plane
        int rem = idx & 1023;
        int n = rem >> 3, q = rem & 7;
        const __half* src = g_wh + (size_t)n * D_DIM + k0 + (p << 6) + (q << 3);
        uint32_t dst = sb + WM_OFF(buf, p) + sw128((n << 7) + (q << 4));
        CP_ASYNC16(dst, src);
    }
}
// repair chunk (KCR=64, hi+lo): 2048 uint4
static __device__ __forceinline__ void issue_w_rep(uint32_t base, int t, int k0) {
#pragma unroll
    for (int i = 0; i < 8; i++) {
        int idx = t + (i << 8);
        int v   = idx >> 10;
        int rem = idx & 1023;
        int n = rem >> 3, q = rem & 7;
        const __half* src = (v ? g_wl : g_wh) + (size_t)n * D_DIM + k0 + (q << 3);
        uint32_t dst = base + (v << 14) + sw128((n << 7) + (q << 4));
        CP_ASYNC16(dst, src);
    }
}

static __device__ __forceinline__ void row_gate(float* lgrow, const float* nsrow,
                                                float* rsrow, float* v8o, float* v9o)
{
    float m = -INFINITY;
    for (int e = 0; e < E_EXP; ++e) {
        float cl = lgrow[e]      * 0.015625f;
        float nr = lgrow[64 + e] * 0.015625f;
        float sd = (nr > 20.f) ? nr : log1pf(__expf(nr));
        float v  = cl + nsrow[e] * sd;
        lgrow[e] = v;
        m = fmaxf(m, v);
    }
    unsigned long long sel = 0ULL;
    float m8 = 0.f, v8 = 0.f;
    for (int kk = 0; kk < K_TOP; ++kk) {
        float best = -INFINITY; int bi = 0;
        for (int e = 0; e < E_EXP; ++e) {
            if (!((sel >> e) & 1ULL)) {
                float v = lgrow[e];
                if (v > best) { best = v; bi = e; }
            }
        }
        sel |= 1ULL << bi;
        if (kk == 0) m8 = best;
        if (kk == K_TOP - 1) v8 = best;
    }
    float v9 = -INFINITY;
    for (int e = 0; e < E_EXP; ++e)
        if (!((sel >> e) & 1ULL)) v9 = fmaxf(v9, lgrow[e]);
    float s8 = 0.f;
    for (int e = 0; e < E_EXP; ++e)
        if ((sel >> e) & 1ULL) s8 += __expf(lgrow[e] - m8);
    float inv8 = 1.f / s8;
    for (int e = 0; e < E_EXP; ++e)
        rsrow[e] = ((sel >> e) & 1ULL) ? __expf(lgrow[e] - m8) * inv8 : 0.f;
    *v8o = v8; *v9o = v9;
}

__global__ __launch_bounds__(256, 2)
void gate_mma_kernel(const float* __restrict__ x,
                     const float* __restrict__ noise,
                     float* __restrict__ out, int out_elems)
{
    extern __shared__ char smem[];
    const uint32_t sb = smem_u32(smem);
    const int t   = threadIdx.x;
    const int wid = t >> 5;
    const int lid = t & 31;
    const int wm  = wid & 1;
    const int wn  = wid >> 1;
    const int row0 = blockIdx.x * TM;
    const float* xp = x + (size_t)row0 * D_DIM;

    float acc[4][4][4];
#pragma unroll
    for (int a = 0; a < 4; a++)
#pragma unroll
        for (int b = 0; b < 4; b++)
#pragma unroll
            for (int c = 0; c < 4; c++) acc[a][b][c] = 0.f;

    const uint32_t xmask     = (uint32_t)(lid & 7) << 4;
    const uint32_t a_rowbase = (uint32_t)(wm * 64 + ((lid >> 3) & 1) * 8 + (lid & 7)) * 128;
    const uint32_t a_kincr   = (uint32_t)(lid >> 4) * 16;
    const uint32_t b_rowbase = (uint32_t)(wn * 32 + ((lid >> 4) << 3) + (lid & 7)) * 128;
    const uint32_t b_kincr   = (uint32_t)((lid >> 3) & 1) * 16;

    const int xr_ = t >> 4;           // row 0..15 (stride 16)
    const int xj_ = t & 15;           // float4 col within 64-elem plane

    issue_w_main(sb, 0, t, 0); CP_COMMIT();

    for (int c = 0; c < NCH; ++c) {
        const int k0 = c * KC;
        __syncthreads();
        // ---- x: 16 float4/thread (2 planes x 8), round to fp16 hi, swizzled ----
#pragma unroll
        for (int p = 0; p < 2; ++p) {
#pragma unroll
            for (int i = 0; i < 8; ++i) {
                int r = xr_ + (i << 4);
                float4 v = *(const float4*)(xp + (size_t)r * D_DIM + k0 + (p << 6) + (xj_ << 2));
                uint32_t sw = sw128((r << 7) + (xj_ << 3));
                *(uint2*)(smem + XP_OFF(p) + sw) =
                    make_uint2(pkh(__float2half(v.x), __float2half(v.y)),
                               pkh(__float2half(v.z), __float2half(v.w)));
            }
        }
        if (c < NCH - 1) { issue_w_main(sb, (c + 1) & 1, t, (c + 1) * KC); CP_COMMIT(); CP_WAIT1(); }
        else             { CP_WAIT0(); }
        __syncthreads();

#pragma unroll
        for (int kss = 0; kss < 8; ++kss) {
            const int p = kss >> 2;
            const int ks = kss & 3;
            const uint32_t wb = sb + WM_OFF(c & 1, p);
            const uint32_t xb = sb + XP_OFF(p);
            const uint32_t boff = (uint32_t)(ks * 32 + b_kincr) ^ xmask;
            uint32_t bH[8];
            LDSM4(&bH[0], wb + b_rowbase + boff);
            LDSM4(&bH[4], wb + b_rowbase + 2048 + boff);
            const uint32_t aoff = (uint32_t)(ks * 32 + a_kincr) ^ xmask;
#pragma unroll
            for (int mt = 0; mt < 4; ++mt) {
                uint32_t aH[4];
                LDSM4(aH, xb + a_rowbase + mt * 2048 + aoff);
#pragma unroll
                for (int nt = 0; nt < 4; ++nt) {
                    int bi = (nt >> 1) * 4 + (nt & 1) * 2;
                    mma16816(acc[mt][nt], aH, bH[bi], bH[bi + 1]);
                }
            }
        }
    }

    // ================= epilogue =================
    __syncthreads();
    float* lg   = (float*)(smem + LG_OFF);
    float* nsrs = (float*)(smem + NS_OFF);

#pragma unroll
    for (int i = 0; i < 32; i++) {
        int idx = t + (i << 8);
        nsrs[(idx >> 6) * 65 + (idx & 63)] = noise[(size_t)row0 * E_EXP + idx];
    }
#pragma unroll
    for (int mt = 0; mt < 4; ++mt) {
        int r = wm * 64 + mt * 16 + (lid >> 2);
#pragma unroll
        for (int nt = 0; nt < 4; ++nt) {
            int c0 = wn * 32 + nt * 8 + (lid & 3) * 2;
            lg[r * 129 + c0]           = acc[mt][nt][0];
            lg[r * 129 + c0 + 1]       = acc[mt][nt][1];
            lg[(r + 8) * 129 + c0]     = acc[mt][nt][2];
            lg[(r + 8) * 129 + c0 + 1] = acc[mt][nt][3];
        }
    }
    __syncthreads();

    double ps_d = 0.0, sq_d = 0.0;
    if (t < TM) {
        const int r = t;
        float v8, v9;
        row_gate(lg + r * 129, nsrs + r * 65, nsrs + r * 65, &v8, &v9);
        float m = -INFINITY;
        for (int e = 0; e < E_EXP; ++e) m = fmaxf(m, lg[r * 129 + e]);
        float s = 0.f;
        for (int e = 0; e < E_EXP; ++e) s += __expf(lg[r * 129 + e] - m);
        float inv = 1.f / s;
        float ps = 0.f, sq = 0.f;
        for (int e = 0; e < E_EXP; ++e) {
            float p = __expf(lg[r * 129 + e] - m) * inv;
            ps += p; sq += p * p;
        }
        ps_d = ps; sq_d = sq;
        if (v8 - v9 < GAP_THETA) {
            int i = atomicAdd(&g_nflag, 1);
            if (i < CAPROWS) g_flagrows[i] = row0 + r;
        }
    }

    __shared__ double wps[4], wsq[4];
#pragma unroll
    for (int o = 16; o > 0; o >>= 1) {
        ps_d += __shfl_down_sync(0xffffffffu, ps_d, o);
        sq_d += __shfl_down_sync(0xffffffffu, sq_d, o);
    }
    if (wid < 4 && lid == 0) { wps[wid] = ps_d; wsq[wid] = sq_d; }
    __syncthreads();
    if (t == 0) {
        g_ps[blockIdx.x] = wps[0] + wps[1] + wps[2] + wps[3];
        g_sq[blockIdx.x] = wsq[0] + wsq[1] + wsq[2] + wsq[3];
    }
#pragma unroll
    for (int i = 0; i < 32; i++) {
        int idx = t + (i << 8);
        size_t o = (size_t)row0 * E_EXP + idx;
        if (o < (size_t)out_elems) out[o] = nsrs[(idx >> 6) * 65 + (idx & 63)];
    }
}

// ---- Phase A: split-K 4-product repair GEMM (unchanged from R13) ----
__global__ __launch_bounds__(256, 2)
void repair_gemm_kernel(const float* __restrict__ x)
{
    extern __shared__ char smem[];
    const uint32_t sb = smem_u32(smem);
    const int t   = threadIdx.x;
    const int wid = t >> 5;
    const int lid = t & 31;
    const int wm  = wid & 1;
    const int wn  = wid >> 1;

    const int nf = min(g_nflag, CAPROWS);
    const int ntiles = (nf + TM - 1) / TM;
    const int nitems = ntiles * SPLITK;

    __shared__ int ridx[TM];

    const uint32_t xmask     = (uint32_t)(lid & 7) << 4;
    const uint32_t a_rowbase = (uint32_t)(wm * 64 + ((lid >> 3) & 1) * 8 + (lid & 7)) * 128;
    const uint32_t a_kincr   = (uint32_t)(lid >> 4) * 16;
    const uint32_t b_rowbase = (uint32_t)(wn * 32 + ((lid >> 4) << 3) + (lid & 7)) * 128;
    const uint32_t b_kincr   = (uint32_t)((lid >> 3) & 1) * 16;
    const int xr_ = t >> 4;
    const int xj_ = t & 15;

    for (int item = blockIdx.x; item < nitems; item += gridDim.x) {
        const int tile  = item >> 4;
        const int slice = item & (SPLITK - 1);
        const int kbase = slice * KPS * KCR;

        __syncthreads();
        if (t < TM) {
            int gi = tile * TM + t;
            ridx[t] = g_flagrows[gi < nf ? gi : nf - 1];
        }
        issue_w_rep(sb + WBR_OFF(0), t, kbase); CP_COMMIT();
        __syncthreads();

        float acc[4][4][4];
#pragma unroll
        for (int a = 0; a < 4; a++)
#pragma unroll
            for (int b = 0; b < 4; b++)
#pragma unroll
                for (int c = 0; c < 4; c++) acc[a][b][c] = 0.f;

        for (int j = 0; j < KPS; ++j) {
            const int k0 = kbase + j * KCR;
            if (j) __syncthreads();
#pragma unroll
            for (int i = 0; i < 8; ++i) {
                int r = xr_ + (i << 4);
                float4 v = *(const float4*)(x + (size_t)ridx[r] * D_DIM + k0 + (xj_ << 2));
                __half h0 = __float2half(v.x), h1 = __float2half(v.y);
                __half h2 = __float2half(v.z), h3 = __float2half(v.w);
                __half l0 = __float2half(v.x - __half2float(h0)), l1 = __float2half(v.y - __half2float(h1));
                __half l2 = __float2half(v.z - __half2float(h2)), l3 = __float2half(v.w - __half2float(h3));
                uint32_t sw = sw128((r << 7) + (xj_ << 3));
                *(uint2*)(smem + 0      + sw) = make_uint2(pkh(h0, h1), pkh(h2, h3));
                *(uint2*)(smem + XL_OFF + sw) = make_uint2(pkh(l0, l1), pkh(l2, l3));
            }
            if (j < KPS - 1) { issue_w_rep(sb + WBR_OFF((j + 1) & 1), t, k0 + KCR); CP_COMMIT(); CP_WAIT1(); }
            else             { CP_WAIT0(); }
            __syncthreads();

            const uint32_t wb = sb + WBR_OFF(j & 1);
#pragma unroll
            for (int ks = 0; ks < 4; ++ks) {
                const uint32_t boff = (uint32_t)(ks * 32 + b_kincr) ^ xmask;
                uint32_t bH[8], bL[8];
                LDSM4(&bH[0], wb + b_rowbase + boff);
                LDSM4(&bH[4], wb + b_rowbase + 2048 + boff);
                LDSM4(&bL[0], wb + 16384 + b_rowbase + boff);
                LDSM4(&bL[4], wb + 16384 + b_rowbase + 2048 + boff);
                const uint32_t aoff = (uint32_t)(ks * 32 + a_kincr) ^ xmask;
#pragma unroll
                for (int mt = 0; mt < 4; ++mt) {
                    uint32_t aH[4], aL[4];
                    LDSM4(aH, sb + 0      + a_rowbase + mt * 2048 + aoff);
                    LDSM4(aL, sb + XL_OFF + a_rowbase + mt * 2048 + aoff);
#pragma unroll
                    for (int nt = 0; nt < 4; ++nt) {
                        int bi = (nt >> 1) * 4 + (nt & 1) * 2;
                        mma16816(acc[mt][nt], aH, bH[bi], bH[bi + 1]);
                        mma16816(acc[mt][nt], aH, bL[bi], bL[bi + 1]);
                        mma16816(acc[mt][nt], aL, bH[bi], bH[bi + 1]);
                        mma16816(acc[mt][nt], aL, bL[bi], bL[bi + 1]);
                    }
                }
            }
        }

        float* dst = g_scratch + ((size_t)slice * MAXTILES + tile) * (TM * NCOL);
#pragma unroll
        for (int mt = 0; mt < 4; ++mt) {
            int r = wm * 64 + mt * 16 + (lid >> 2);
#pragma unroll
            for (int nt = 0; nt < 4; ++nt) {
                int c0 = wn * 32 + nt * 8 + (lid & 3) * 2;
                dst[r * NCOL + c0]           = acc[mt][nt][0];
                dst[r * NCOL + c0 + 1]       = acc[mt][nt][1];
                dst[(r + 8) * NCOL + c0]     = acc[mt][nt][2];
                dst[(r + 8) * NCOL + c0 + 1] = acc[mt][nt][3];
            }
        }
    }
}

// ---- Phase B: deterministic slice-sum + row_gate + scatter ----
__global__ __launch_bounds__(256, 2)
void repair_fix_kernel(const float* __restrict__ noise, float* __restrict__ out)
{
    extern __shared__ char smem[];
    float* lg   = (float*)(smem + LG_OFF);
    float* nsrs = (float*)(smem + NS_OFF);
    const int t = threadIdx.x;
    const int nf = min(g_nflag, CAPROWS);
    const int ntiles = (nf + TM - 1) / TM;

    for (int tile = blockIdx.x; tile < ntiles; tile += gridDim.x) {
        __syncthreads();
        for (int idx = t; idx < TM * NCOL; idx += 256) {
            int r = idx >> 7, c = idx & 127;
            float s = 0.f;
            const float* src = g_scratch + (size_t)tile * (TM * NCOL) + idx;
#pragma unroll
            for (int sl = 0; sl < SPLITK; ++sl)
                s += src[(size_t)sl * MAXTILES * TM * NCOL];
            lg[r * 129 + c] = s;
        }
        if (t < TM) {
            int gi = tile * TM + t;
            if (gi < nf) {
                const float* nrow = noise + (size_t)g_flagrows[gi] * E_EXP;
                for (int e = 0; e < E_EXP; ++e) nsrs[t * 65 + e] = nrow[e];
            }
        }
        __syncthreads();
        if (t < TM) {
            int gi = tile * TM + t;
            if (gi < nf) {
                float v8, v9;
                row_gate(lg + t * 129, nsrs + t * 65, nsrs + t * 65, &v8, &v9);
                float* orow = out + (size_t)g_flagrows[gi] * E_EXP;
                for (int e = 0; e < E_EXP; ++e) orow[e] = nsrs[t * 65 + e];
            }
        }
    }
}

__global__ void finalize_kernel(float* __restrict__ out, int out_elems)
{
    __shared__ double ssum[256], ssq[256];
    double a = 0.0, b = 0.0;
    for (int i = threadIdx.x; i < NBLK; i += 256) { a += g_ps[i]; b += g_sq[i]; }
    ssum[threadIdx.x] = a; ssq[threadIdx.x] = b;
    __syncthreads();
    for (int s = 128; s > 0; s >>= 1) {
        if (threadIdx.x < s) {
            ssum[threadIdx.x] += ssum[threadIdx.x + s];
            ssq[threadIdx.x]  += ssq[threadIdx.x + s];
        }
        __syncthreads();
    }
    if (threadIdx.x == 0) {
        double n    = (double)B_TOK * (double)E_EXP;
        double mean = ssum[0] / n;
        double var  = (ssq[0] - n * mean * mean) / (n - 1.0);
        float loss  = (float)(var / (mean * mean + 1e-10));
        long long base = (long long)B_TOK * E_EXP;
        if (out_elems == 1) out[0] = loss;
        else for (long long i = base; i < (long long)out_elems; i++) out[i] = loss;
    }
}

extern "C" void kernel_launch(void* const* d_in, const int* in_sizes, int n_in,
                              void* d_out, int out_size)
{
    const float* x  = (const float*)d_in[0];
    const float* wg = (const float*)d_in[1];
    const float* wn = (const float*)d_in[2];
    const float* nz = (const float*)d_in[3];
    float* out = (float*)d_out;

    cudaFuncSetAttribute(gate_mma_kernel,    cudaFuncAttributeMaxDynamicSharedMemorySize, SMEM_BYTES);
    cudaFuncSetAttribute(repair_gemm_kernel, cudaFuncAttributeMaxDynamicSharedMemorySize, SMEM_BYTES);
    cudaFuncSetAttribute(repair_fix_kernel,  cudaFuncAttributeMaxDynamicSharedMemorySize, SMEM_BYTES);

    reset_kernel<<<1, 32>>>();
    wconv_kernel<<<(D_DIM * E_EXP + 255) / 256, 256>>>(wg, wn);
    gate_mma_kernel<<<NBLK, 256, SMEM_BYTES>>>(x, nz, out, out_size);
    repair_gemm_kernel<<<NBLK, 256, SMEM_BYTES>>>(x);
    repair_fix_kernel<<<64, 256, SMEM_BYTES>>>(nz, out);
    finalize_kernel<<<1, 256>>>(out, out_size);
}

// round 16
// speedup vs baseline: 1.2669x; 1.0737x over previous
#include <cuda_runtime.h>
#include <cuda_fp16.h>
#include <math.h>
#include <stdint.h>

#define B_TOK 65536
#define D_DIM 4096
#define E_EXP 64
#define K_TOP 8

#define TM   128
#define NBLK (B_TOK / TM)        // 512 CTAs
#define KC   128                 // K per main chunk: two 128B SW128 planes
#define NCH  (D_DIM / KC)        // 32 chunks
#define KCR  64                  // repair chunk
#define NCHR (D_DIM / KCR)       // 64
#define NCOL 128
#define GAP_THETA 3e-3f          // ~7 sigma of 1-product logit error
#define SPLITK   16
#define KPS      (NCHR / SPLITK) // 4 repair chunks per slice
#define MAXTILES 64
#define CAPROWS  (MAXTILES * TM)

__device__ __half g_wh[NCOL * D_DIM];
__device__ __half g_wl[NCOL * D_DIM];
__device__ double g_ps[NBLK];
__device__ double g_sq[NBLK];
__device__ int    g_nflag;
__device__ int    g_flagrows[CAPROWS];
__device__ float  g_scratch[(size_t)SPLITK * MAXTILES * TM * NCOL];

// main: X planes 0,16K | W buf b at 32768+b*32768, planes +0,+16K   (96KB)
// repair: XH 0..16K, XL 16K..32K | W buf b: 32768 + b*32768
// epilogue overlay: LG 0 float[128][129] | NSRS 66048 float[128][65]
#define XP_OFF(p)    ((p) * 16384)
#define WM_OFF(b,p)  (32768 + (b) * 32768 + (p) * 16384)
#define XL_OFF 16384
#define WBR_OFF(b)   (32768 + (b) * 32768)
#define LG_OFF 0
#define NS_OFF 66048
#define SMEM_BYTES (66048 + 33280)   // 99328

static __device__ __forceinline__ uint32_t smem_u32(const void* p) {
    uint32_t a;
    asm("{ .reg .u64 t; cvta.to.shared.u64 t, %1; cvt.u32.u64 %0, t; }" : "=r"(a) : "l"(p));
    return a;
}
static __device__ __forceinline__ uint32_t sw128(uint32_t off) { return off ^ ((off >> 3) & 0x70); }
static __device__ __forceinline__ uint32_t pkh(__half a, __half b) {
    return (uint32_t)__half_as_ushort(a) | ((uint32_t)__half_as_ushort(b) << 16);
}

#define LDSM4(r, a) \
    asm volatile("ldmatrix.sync.aligned.m8n8.x4.shared.b16 {%0,%1,%2,%3}, [%4];" \
        : "=r"((r)[0]), "=r"((r)[1]), "=r"((r)[2]), "=r"((r)[3]) : "r"(a))

static __device__ __forceinline__ void mma16816(float* d, const uint32_t* a, uint32_t b0, uint32_t b1) {
    asm volatile("mma.sync.aligned.m16n8k16.row.col.f32.f16.f16.f32 "
        "{%0,%1,%2,%3}, {%4,%5,%6,%7}, {%8,%9}, {%0,%1,%2,%3};"
        : "+f"(d[0]), "+f"(d[1]), "+f"(d[2]), "+f"(d[3])
        : "r"(a[0]), "r"(a[1]), "r"(a[2]), "r"(a[3]), "r"(b0), "r"(b1));
}

#define CP_ASYNC16(dst, src) asm volatile("cp.async.cg.shared.global [%0], [%1], 16;" :: "r"(dst), "l"(src) : "memory")
#define CP_COMMIT()          asm volatile("cp.async.commit_group;" ::: "memory")
#define CP_WAIT1()           asm volatile("cp.async.wait_group 1;" ::: "memory")
#define CP_WAIT0()           asm volatile("cp.async.wait_group 0;" ::: "memory")

// reset folded in: block 0 / thread 0 clears the flag counter
__global__ void wconv_kernel(const float* __restrict__ wg, const float* __restrict__ wn)
{
    if (blockIdx.x == 0 && threadIdx.x == 0) g_nflag = 0;
    int idx = blockIdx.x * 256 + threadIdx.x;
    if (idx >= D_DIM * E_EXP) return;
    int k = idx >> 6, n = idx & 63;
    float f = wg[idx] * 64.f;
    __half h = __float2half(f);
    g_wh[(size_t)n * D_DIM + k] = h;
    g_wl[(size_t)n * D_DIM + k] = __float2half(f - __half2float(h));
    f = wn[idx] * 64.f;
    h = __float2half(f);
    g_wh[(size_t)(64 + n) * D_DIM + k] = h;
    g_wl[(size_t)(64 + n) * D_DIM + k] = __float2half(f - __half2float(h));
}

// main chunk (KC=128, hi only): 2048 uint4 (2 planes x 1024); 256 thr -> 8 each
static __device__ __forceinline__ void issue_w_main(uint32_t sb, int buf, int t, int k0) {
#pragma unroll
    for (int i = 0; i < 8; i++) {
        int idx = t + (i << 8);                 // 0..2047
        int p   = idx >> 10;                    // plane
        int rem = idx & 1023;
        int n = rem >> 3, q = rem & 7;
        const __half* src = g_wh + (size_t)n * D_DIM + k0 + (p << 6) + (q << 3);
        uint32_t dst = sb + WM_OFF(buf, p) + sw128((n << 7) + (q << 4));
        CP_ASYNC16(dst, src);
    }
}
// repair chunk (KCR=64, hi+lo): 2048 uint4
static __device__ __forceinline__ void issue_w_rep(uint32_t base, int t, int k0) {
#pragma unroll
    for (int i = 0; i < 8; i++) {
        int idx = t + (i << 8);
        int v   = idx >> 10;
        int rem = idx & 1023;
        int n = rem >> 3, q = rem & 7;
        const __half* src = (v ? g_wl : g_wh) + (size_t)n * D_DIM + k0 + (q << 3);
        uint32_t dst = base + (v << 14) + sw128((n << 7) + (q << 4));
        CP_ASYNC16(dst, src);
    }
}

static __device__ __forceinline__ void row_gate(float* lgrow, const float* nsrow,
                                                float* rsrow, float* v8o, float* v9o)
{
    float m = -INFINITY;
    for (int e = 0; e < E_EXP; ++e) {
        float cl = lgrow[e]      * 0.015625f;
        float nr = lgrow[64 + e] * 0.015625f;
        float sd = (nr > 20.f) ? nr : log1pf(__expf(nr));
        float v  = cl + nsrow[e] * sd;
        lgrow[e] = v;
        m = fmaxf(m, v);
    }
    unsigned long long sel = 0ULL;
    float m8 = 0.f, v8 = 0.f;
    for (int kk = 0; kk < K_TOP; ++kk) {
        float best = -INFINITY; int bi = 0;
        for (int e = 0; e < E_EXP; ++e) {
            if (!((sel >> e) & 1ULL)) {
                float v = lgrow[e];
                if (v > best) { best = v; bi = e; }
            }
        }
        sel |= 1ULL << bi;
        if (kk == 0) m8 = best;
        if (kk == K_TOP - 1) v8 = best;
    }
    float v9 = -INFINITY;
    for (int e = 0; e < E_EXP; ++e)
        if (!((sel >> e) & 1ULL)) v9 = fmaxf(v9, lgrow[e]);
    float s8 = 0.f;
    for (int e = 0; e < E_EXP; ++e)
        if ((sel >> e) & 1ULL) s8 += __expf(lgrow[e] - m8);
    float inv8 = 1.f / s8;
    for (int e = 0; e < E_EXP; ++e)
        rsrow[e] = ((sel >> e) & 1ULL) ? __expf(lgrow[e] - m8) * inv8 : 0.f;
    *v8o = v8; *v9o = v9;
}

__global__ __launch_bounds__(256, 2)
void gate_mma_kernel(const float* __restrict__ x,
                     const float* __restrict__ noise,
                     float* __restrict__ out, int out_elems)
{
    extern __shared__ char smem[];
    const uint32_t sb = smem_u32(smem);
    const int t   = threadIdx.x;
    const int wid = t >> 5;
    const int lid = t & 31;
    const int wm  = wid & 1;
    const int wn  = wid >> 1;
    const int row0 = blockIdx.x * TM;
    const float* xp = x + (size_t)row0 * D_DIM;

    float acc[4][4][4];
#pragma unroll
    for (int a = 0; a < 4; a++)
#pragma unroll
        for (int b = 0; b < 4; b++)
#pragma unroll
            for (int c = 0; c < 4; c++) acc[a][b][c] = 0.f;

    const uint32_t xmask     = (uint32_t)(lid & 7) << 4;
    const uint32_t a_rowbase = (uint32_t)(wm * 64 + ((lid >> 3) & 1) * 8 + (lid & 7)) * 128;
    const uint32_t a_kincr   = (uint32_t)(lid >> 4) * 16;
    const uint32_t b_rowbase = (uint32_t)(wn * 32 + ((lid >> 4) << 3) + (lid & 7)) * 128;
    const uint32_t b_kincr   = (uint32_t)((lid >> 3) & 1) * 16;

    const int xr_ = t >> 4;           // row 0..15 (stride 16)
    const int xj_ = t & 15;           // float4 col within 64-elem plane

    issue_w_main(sb, 0, t, 0); CP_COMMIT();

    for (int c = 0; c < NCH; ++c) {
        const int k0 = c * KC;
        __syncthreads();
#pragma unroll
        for (int p = 0; p < 2; ++p) {
#pragma unroll
            for (int i = 0; i < 8; ++i) {
                int r = xr_ + (i << 4);
                float4 v = *(const float4*)(xp + (size_t)r * D_DIM + k0 + (p << 6) + (xj_ << 2));
                uint32_t sw = sw128((r << 7) + (xj_ << 3));
                *(uint2*)(smem + XP_OFF(p) + sw) =
                    make_uint2(pkh(__float2half(v.x), __float2half(v.y)),
                               pkh(__float2half(v.z), __float2half(v.w)));
            }
        }
        if (c < NCH - 1) { issue_w_main(sb, (c + 1) & 1, t, (c + 1) * KC); CP_COMMIT(); CP_WAIT1(); }
        else             { CP_WAIT0(); }
        __syncthreads();

#pragma unroll
        for (int kss = 0; kss < 8; ++kss) {
            const int p = kss >> 2;
            const int ks = kss & 3;
            const uint32_t wb = sb + WM_OFF(c & 1, p);
            const uint32_t xb = sb + XP_OFF(p);
            const uint32_t boff = (uint32_t)(ks * 32 + b_kincr) ^ xmask;
            uint32_t bH[8];
            LDSM4(&bH[0], wb + b_rowbase + boff);
            LDSM4(&bH[4], wb + b_rowbase + 2048 + boff);
            const uint32_t aoff = (uint32_t)(ks * 32 + a_kincr) ^ xmask;
#pragma unroll
            for (int mt = 0; mt < 4; ++mt) {
                uint32_t aH[4];
                LDSM4(aH, xb + a_rowbase + mt * 2048 + aoff);
#pragma unroll
                for (int nt = 0; nt < 4; ++nt) {
                    int bi = (nt >> 1) * 4 + (nt & 1) * 2;
                    mma16816(acc[mt][nt], aH, bH[bi], bH[bi + 1]);
                }
            }
        }
    }

    // ================= epilogue =================
    __syncthreads();
    float* lg   = (float*)(smem + LG_OFF);
    float* nsrs = (float*)(smem + NS_OFF);

#pragma unroll
    for (int i = 0; i < 32; i++) {
        int idx = t + (i << 8);
        nsrs[(idx >> 6) * 65 + (idx & 63)] = noise[(size_t)row0 * E_EXP + idx];
    }
#pragma unroll
    for (int mt = 0; mt < 4; ++mt) {
        int r = wm * 64 + mt * 16 + (lid >> 2);
#pragma unroll
        for (int nt = 0; nt < 4; ++nt) {
            int c0 = wn * 32 + nt * 8 + (lid & 3) * 2;
            lg[r * 129 + c0]           = acc[mt][nt][0];
            lg[r * 129 + c0 + 1]       = acc[mt][nt][1];
            lg[(r + 8) * 129 + c0]     = acc[mt][nt][2];
            lg[(r + 8) * 129 + c0 + 1] = acc[mt][nt][3];
        }
    }
    __syncthreads();

    double ps_d = 0.0, sq_d = 0.0;
    if (t < TM) {
        const int r = t;
        float v8, v9;
        row_gate(lg + r * 129, nsrs + r * 65, nsrs + r * 65, &v8, &v9);
        float m = -INFINITY;
        for (int e = 0; e < E_EXP; ++e) m = fmaxf(m, lg[r * 129 + e]);
        float s = 0.f;
        for (int e = 0; e < E_EXP; ++e) s += __expf(lg[r * 129 + e] - m);
        float inv = 1.f / s;
        float ps = 0.f, sq = 0.f;
        for (int e = 0; e < E_EXP; ++e) {
            float p = __expf(lg[r * 129 + e] - m) * inv;
            ps += p; sq += p * p;
        }
        ps_d = ps; sq_d = sq;
        if (v8 - v9 < GAP_THETA) {
            int i = atomicAdd(&g_nflag, 1);
            if (i < CAPROWS) g_flagrows[i] = row0 + r;
        }
    }

    __shared__ double wps[4], wsq[4];
#pragma unroll
    for (int o = 16; o > 0; o >>= 1) {
        ps_d += __shfl_down_sync(0xffffffffu, ps_d, o);
        sq_d += __shfl_down_sync(0xffffffffu, sq_d, o);
    }
    if (wid < 4 && lid == 0) { wps[wid] = ps_d; wsq[wid] = sq_d; }
    __syncthreads();
    if (t == 0) {
        g_ps[blockIdx.x] = wps[0] + wps[1] + wps[2] + wps[3];
        g_sq[blockIdx.x] = wsq[0] + wsq[1] + wsq[2] + wsq[3];
    }
#pragma unroll
    for (int i = 0; i < 32; i++) {
        int idx = t + (i << 8);
        size_t o = (size_t)row0 * E_EXP + idx;
        if (o < (size_t)out_elems) out[o] = nsrs[(idx >> 6) * 65 + (idx & 63)];
    }
}

// ---- Phase A: split-K 4-product repair GEMM ----
__global__ __launch_bounds__(256, 2)
void repair_gemm_kernel(const float* __restrict__ x)
{
    extern __shared__ char smem[];
    const uint32_t sb = smem_u32(smem);
    const int t   = threadIdx.x;
    const int wid = t >> 5;
    const int lid = t & 31;
    const int wm  = wid & 1;
    const int wn  = wid >> 1;

    const int nf = min(g_nflag, CAPROWS);
    const int ntiles = (nf + TM - 1) / TM;
    const int nitems = ntiles * SPLITK;

    __shared__ int ridx[TM];

    const uint32_t xmask     = (uint32_t)(lid & 7) << 4;
    const uint32_t a_rowbase = (uint32_t)(wm * 64 + ((lid >> 3) & 1) * 8 + (lid & 7)) * 128;
    const uint32_t a_kincr   = (uint32_t)(lid >> 4) * 16;
    const uint32_t b_rowbase = (uint32_t)(wn * 32 + ((lid >> 4) << 3) + (lid & 7)) * 128;
    const uint32_t b_kincr   = (uint32_t)((lid >> 3) & 1) * 16;
    const int xr_ = t >> 4;
    const int xj_ = t & 15;

    for (int item = blockIdx.x; item < nitems; item += gridDim.x) {
        const int tile  = item >> 4;
        const int slice = item & (SPLITK - 1);
        const int kbase = slice * KPS * KCR;

        __syncthreads();
        if (t < TM) {
            int gi = tile * TM + t;
            ridx[t] = g_flagrows[gi < nf ? gi : nf - 1];
        }
        issue_w_rep(sb + WBR_OFF(0), t, kbase); CP_COMMIT();
        __syncthreads();

        float acc[4][4][4];
#pragma unroll
        for (int a = 0; a < 4; a++)
#pragma unroll
            for (int b = 0; b < 4; b++)
#pragma unroll
                for (int c = 0; c < 4; c++) acc[a][b][c] = 0.f;

        for (int j = 0; j < KPS; ++j) {
            const int k0 = kbase + j * KCR;
            if (j) __syncthreads();
#pragma unroll
            for (int i = 0; i < 8; ++i) {
                int r = xr_ + (i << 4);
                float4 v = *(const float4*)(x + (size_t)ridx[r] * D_DIM + k0 + (xj_ << 2));
                __half h0 = __float2half(v.x), h1 = __float2half(v.y);
                __half h2 = __float2half(v.z), h3 = __float2half(v.w);
                __half l0 = __float2half(v.x - __half2float(h0)), l1 = __float2half(v.y - __half2float(h1));
                __half l2 = __float2half(v.z - __half2float(h2)), l3 = __float2half(v.w - __half2float(h3));
                uint32_t sw = sw128((r << 7) + (xj_ << 3));
                *(uint2*)(smem + 0      + sw) = make_uint2(pkh(h0, h1), pkh(h2, h3));
                *(uint2*)(smem + XL_OFF + sw) = make_uint2(pkh(l0, l1), pkh(l2, l3));
            }
            if (j < KPS - 1) { issue_w_rep(sb + WBR_OFF((j + 1) & 1), t, k0 + KCR); CP_COMMIT(); CP_WAIT1(); }
            else             { CP_WAIT0(); }
            __syncthreads();

            const uint32_t wb = sb + WBR_OFF(j & 1);
#pragma unroll
            for (int ks = 0; ks < 4; ++ks) {
                const uint32_t boff = (uint32_t)(ks * 32 + b_kincr) ^ xmask;
                uint32_t bH[8], bL[8];
                LDSM4(&bH[0], wb + b_rowbase + boff);
                LDSM4(&bH[4], wb + b_rowbase + 2048 + boff);
                LDSM4(&bL[0], wb + 16384 + b_rowbase + boff);
                LDSM4(&bL[4], wb + 16384 + b_rowbase + 2048 + boff);
                const uint32_t aoff = (uint32_t)(ks * 32 + a_kincr) ^ xmask;
#pragma unroll
                for (int mt = 0; mt < 4; ++mt) {
                    uint32_t aH[4], aL[4];
                    LDSM4(aH, sb + 0      + a_rowbase + mt * 2048 + aoff);
                    LDSM4(aL, sb + XL_OFF + a_rowbase + mt * 2048 + aoff);
#pragma unroll
                    for (int nt = 0; nt < 4; ++nt) {
                        int bi = (nt >> 1) * 4 + (nt & 1) * 2;
                        mma16816(acc[mt][nt], aH, bH[bi], bH[bi + 1]);
                        mma16816(acc[mt][nt], aH, bL[bi], bL[bi + 1]);
                        mma16816(acc[mt][nt], aL, bH[bi], bH[bi + 1]);
                        mma16816(acc[mt][nt], aL, bL[bi], bL[bi + 1]);
                    }
                }
            }
        }

        float* dst = g_scratch + ((size_t)slice * MAXTILES + tile) * (TM * NCOL);
#pragma unroll
        for (int mt = 0; mt < 4; ++mt) {
            int r = wm * 64 + mt * 16 + (lid >> 2);
#pragma unroll
            for (int nt = 0; nt < 4; ++nt) {
                int c0 = wn * 32 + nt * 8 + (lid & 3) * 2;
                dst[r * NCOL + c0]           = acc[mt][nt][0];
                dst[r * NCOL + c0 + 1]       = acc[mt][nt][1];
                dst[(r + 8) * NCOL + c0]     = acc[mt][nt][2];
                dst[(r + 8) * NCOL + c0 + 1] = acc[mt][nt][3];
            }
        }
    }
}

// ---- Phase B: deterministic slice-sum + row_gate + scatter ----
__global__ __launch_bounds__(256, 2)
void repair_fix_kernel(const float* __restrict__ noise, float* __restrict__ out)
{
    extern __shared__ char smem[];
    float* lg   = (float*)(smem + LG_OFF);
    float* nsrs = (float*)(smem + NS_OFF);
    const int t = threadIdx.x;
    const int nf = min(g_nflag, CAPROWS);
    const int ntiles = (nf + TM - 1) / TM;

    for (int tile = blockIdx.x; tile < ntiles; tile += gridDim.x) {
        __syncthreads();
        for (int idx = t; idx < TM * NCOL; idx += 256) {
            int r = idx >> 7, c = idx & 127;
            float s = 0.f;
            const float* src = g_scratch + (size_t)tile * (TM * NCOL) + idx;
#pragma unroll
            for (int sl = 0; sl < SPLITK; ++sl)
                s += src[(size_t)sl * MAXTILES * TM * NCOL];
            lg[r * 129 + c] = s;
        }
        if (t < TM) {
            int gi = tile * TM + t;
            if (gi < nf) {
                const float* nrow = noise + (size_t)g_flagrows[gi] * E_EXP;
                for (int e = 0; e < E_EXP; ++e) nsrs[t * 65 + e] = nrow[e];
            }
        }
        __syncthreads();
        if (t < TM) {
            int gi = tile * TM + t;
            if (gi < nf) {
                float v8, v9;
                row_gate(lg + t * 129, nsrs + t * 65, nsrs + t * 65, &v8, &v9);
                float* orow = out + (size_t)g_flagrows[gi] * E_EXP;
                for (int e = 0; e < E_EXP; ++e) orow[e] = nsrs[t * 65 + e];
            }
        }
    }
}

__global__ void finalize_kernel(float* __restrict__ out, int out_elems)
{
    __shared__ double ssum[256], ssq[256];
    double a = 0.0, b = 0.0;
    for (int i = threadIdx.x; i < NBLK; i += 256) { a += g_ps[i]; b += g_sq[i]; }
    ssum[threadIdx.x] = a; ssq[threadIdx.x] = b;
    __syncthreads();
    for (int s = 128; s > 0; s >>= 1) {
        if (threadIdx.x < s) {
            ssum[threadIdx.x] += ssum[threadIdx.x + s];
            ssq[threadIdx.x]  += ssq[threadIdx.x + s];
        }
        __syncthreads();
    }
    if (threadIdx.x == 0) {
        double n    = (double)B_TOK * (double)E_EXP;
        double mean = ssum[0] / n;
        double var  = (ssq[0] - n * mean * mean) / (n - 1.0);
        float loss  = (float)(var / (mean * mean + 1e-10));
        long long base = (long long)B_TOK * E_EXP;
        if (out_elems == 1) out[0] = loss;
        else for (long long i = base; i < (long long)out_elems; i++) out[i] = loss;
    }
}

extern "C" void kernel_launch(void* const* d_in, const int* in_sizes, int n_in,
                              void* d_out, int out_size)
{
    const float* x  = (const float*)d_in[0];
    const float* wg = (const float*)d_in[1];
    const float* wn = (const float*)d_in[2];
    const float* nz = (const float*)d_in[3];
    float* out = (float*)d_out;

    cudaFuncSetAttribute(gate_mma_kernel,    cudaFuncAttributeMaxDynamicSharedMemorySize, SMEM_BYTES);
    cudaFuncSetAttribute(repair_gemm_kernel, cudaFuncAttributeMaxDynamicSharedMemorySize, SMEM_BYTES);
    cudaFuncSetAttribute(repair_fix_kernel,  cudaFuncAttributeMaxDynamicSharedMemorySize, SMEM_BYTES);

    wconv_kernel<<<(D_DIM * E_EXP + 255) / 256, 256>>>(wg, wn);
    gate_mma_kernel<<<NBLK, 256, SMEM_BYTES>>>(x, nz, out, out_size);
    repair_gemm_kernel<<<NBLK, 256, SMEM_BYTES>>>(x);
    repair_fix_kernel<<<32, 256, SMEM_BYTES>>>(nz, out);
    finalize_kernel<<<1, 256>>>(out, out_size);
}

// round 17
// speedup vs baseline: 1.3450x; 1.0616x over previous
#include <cuda_runtime.h>
#include <cuda_fp16.h>
#include <math.h>
#include <stdint.h>

#define B_TOK 65536
#define D_DIM 4096
#define E_EXP 64
#define K_TOP 8

#define TM   128
#define NBLK (B_TOK / TM)        // 512 CTAs
#define KC   128                 // K per main chunk: two 128B SW128 planes
#define NCH  (D_DIM / KC)        // 32 chunks
#define KCR  64                  // repair chunk
#define NCHR (D_DIM / KCR)       // 64
#define NCOL 128
#define GAP_THETA 3e-3f          // ~7 sigma of 1-product logit error
#define SPLITK   16
#define KPS      (NCHR / SPLITK) // 4 repair chunks per slice
#define MAXTILES 64
#define CAPROWS  (MAXTILES * TM)
#define FIXROWS  8               // rows per Phase-B work item
#define FIXSUB   (TM / FIXROWS)  // 16 row-groups per tile

__device__ __half g_wh[NCOL * D_DIM];
__device__ __half g_wl[NCOL * D_DIM];
__device__ double g_ps[NBLK];
__device__ double g_sq[NBLK];
__device__ int    g_nflag;
__device__ int    g_flagrows[CAPROWS];
__device__ float  g_scratch[(size_t)SPLITK * MAXTILES * TM * NCOL];

// main: X planes 0,16K | W buf b at 32768+b*32768, planes +0,+16K   (96KB)
// repair: XH 0..16K, XL 16K..32K | W buf b: 32768 + b*32768
// epilogue overlay: LG 0 float[128][129] | NSRS 66048 float[128][65]
#define XP_OFF(p)    ((p) * 16384)
#define WM_OFF(b,p)  (32768 + (b) * 32768 + (p) * 16384)
#define XL_OFF 16384
#define WBR_OFF(b)   (32768 + (b) * 32768)
#define LG_OFF 0
#define NS_OFF 66048
#define SMEM_BYTES (66048 + 33280)   // 99328

static __device__ __forceinline__ uint32_t smem_u32(const void* p) {
    uint32_t a;
    asm("{ .reg .u64 t; cvta.to.shared.u64 t, %1; cvt.u32.u64 %0, t; }" : "=r"(a) : "l"(p));
    return a;
}
static __device__ __forceinline__ uint32_t sw128(uint32_t off) { return off ^ ((off >> 3) & 0x70); }
static __device__ __forceinline__ uint32_t pkh(__half a, __half b) {
    return (uint32_t)__half_as_ushort(a) | ((uint32_t)__half_as_ushort(b) << 16);
}

#define LDSM4(r, a) \
    asm volatile("ldmatrix.sync.aligned.m8n8.x4.shared.b16 {%0,%1,%2,%3}, [%4];" \
        : "=r"((r)[0]), "=r"((r)[1]), "=r"((r)[2]), "=r"((r)[3]) : "r"(a))

static __device__ __forceinline__ void mma16816(float* d, const uint32_t* a, uint32_t b0, uint32_t b1) {
    asm volatile("mma.sync.aligned.m16n8k16.row.col.f32.f16.f16.f32 "
        "{%0,%1,%2,%3}, {%4,%5,%6,%7}, {%8,%9}, {%0,%1,%2,%3};"
        : "+f"(d[0]), "+f"(d[1]), "+f"(d[2]), "+f"(d[3])
        : "r"(a[0]), "r"(a[1]), "r"(a[2]), "r"(a[3]), "r"(b0), "r"(b1));
}

#define CP_ASYNC16(dst, src) asm volatile("cp.async.cg.shared.global [%0], [%1], 16;" :: "r"(dst), "l"(src) : "memory")
#define CP_COMMIT()          asm volatile("cp.async.commit_group;" ::: "memory")
#define CP_WAIT1()           asm volatile("cp.async.wait_group 1;" ::: "memory")
#define CP_WAIT0()           asm volatile("cp.async.wait_group 0;" ::: "memory")

// reset folded in: block 0 / thread 0 clears the flag counter
__global__ void wconv_kernel(const float* __restrict__ wg, const float* __restrict__ wn)
{
    if (blockIdx.x == 0 && threadIdx.x == 0) g_nflag = 0;
    int idx = blockIdx.x * 256 + threadIdx.x;
    if (idx >= D_DIM * E_EXP) return;
    int k = idx >> 6, n = idx & 63;
    float f = wg[idx] * 64.f;
    __half h = __float2half(f);
    g_wh[(size_t)n * D_DIM + k] = h;
    g_wl[(size_t)n * D_DIM + k] = __float2half(f - __half2float(h));
    f = wn[idx] * 64.f;
    h = __float2half(f);
    g_wh[(size_t)(64 + n) * D_DIM + k] = h;
    g_wl[(size_t)(64 + n) * D_DIM + k] = __float2half(f - __half2float(h));
}

// main chunk (KC=128, hi only): 2048 uint4 (2 planes x 1024); 256 thr -> 8 each
static __device__ __forceinline__ void issue_w_main(uint32_t sb, int buf, int t, int k0) {
#pragma unroll
    for (int i = 0; i < 8; i++) {
        int idx = t + (i << 8);                 // 0..2047
        int p   = idx >> 10;                    // plane
        int rem = idx & 1023;
        int n = rem >> 3, q = rem & 7;
        const __half* src = g_wh + (size_t)n * D_DIM + k0 + (p << 6) + (q << 3);
        uint32_t dst = sb + WM_OFF(buf, p) + sw128((n << 7) + (q << 4));
        CP_ASYNC16(dst, src);
    }
}
// repair chunk (KCR=64, hi+lo): 2048 uint4
static __device__ __forceinline__ void issue_w_rep(uint32_t base, int t, int k0) {
#pragma unroll
    for (int i = 0; i < 8; i++) {
        int idx = t + (i << 8);
        int v   = idx >> 10;
        int rem = idx & 1023;
        int n = rem >> 3, q = rem & 7;
        const __half* src = (v ? g_wl : g_wh) + (size_t)n * D_DIM + k0 + (q << 3);
        uint32_t dst = base + (v << 14) + sw128((n << 7) + (q << 4));
        CP_ASYNC16(dst, src);
    }
}

static __device__ __forceinline__ void row_gate(float* lgrow, const float* nsrow,
                                                float* rsrow, float* v8o, float* v9o)
{
    float m = -INFINITY;
    for (int e = 0; e < E_EXP; ++e) {
        float cl = lgrow[e]      * 0.015625f;
        float nr = lgrow[64 + e] * 0.015625f;
        float sd = (nr > 20.f) ? nr : log1pf(__expf(nr));
        float v  = cl + nsrow[e] * sd;
        lgrow[e] = v;
        m = fmaxf(m, v);
    }
    unsigned long long sel = 0ULL;
    float m8 = 0.f, v8 = 0.f;
    for (int kk = 0; kk < K_TOP; ++kk) {
        float best = -INFINITY; int bi = 0;
        for (int e = 0; e < E_EXP; ++e) {
            if (!((sel >> e) & 1ULL)) {
                float v = lgrow[e];
                if (v > best) { best = v; bi = e; }
            }
        }
        sel |= 1ULL << bi;
        if (kk == 0) m8 = best;
        if (kk == K_TOP - 1) v8 = best;
    }
    float v9 = -INFINITY;
    for (int e = 0; e < E_EXP; ++e)
        if (!((sel >> e) & 1ULL)) v9 = fmaxf(v9, lgrow[e]);
    float s8 = 0.f;
    for (int e = 0; e < E_EXP; ++e)
        if ((sel >> e) & 1ULL) s8 += __expf(lgrow[e] - m8);
    float inv8 = 1.f / s8;
    for (int e = 0; e < E_EXP; ++e)
        rsrow[e] = ((sel >> e) & 1ULL) ? __expf(lgrow[e] - m8) * inv8 : 0.f;
    *v8o = v8; *v9o = v9;
}

__global__ __launch_bounds__(256, 2)
void gate_mma_kernel(const float* __restrict__ x,
                     const float* __restrict__ noise,
                     float* __restrict__ out, int out_elems)
{
    extern __shared__ char smem[];
    const uint32_t sb = smem_u32(smem);
    const int t   = threadIdx.x;
    const int wid = t >> 5;
    const int lid = t & 31;
    const int wm  = wid & 1;
    const int wn  = wid >> 1;
    const int row0 = blockIdx.x * TM;
    const float* xp = x + (size_t)row0 * D_DIM;

    float acc[4][4][4];
#pragma unroll
    for (int a = 0; a < 4; a++)
#pragma unroll
        for (int b = 0; b < 4; b++)
#pragma unroll
            for (int c = 0; c < 4; c++) acc[a][b][c] = 0.f;

    const uint32_t xmask     = (uint32_t)(lid & 7) << 4;
    const uint32_t a_rowbase = (uint32_t)(wm * 64 + ((lid >> 3) & 1) * 8 + (lid & 7)) * 128;
    const uint32_t a_kincr   = (uint32_t)(lid >> 4) * 16;
    const uint32_t b_rowbase = (uint32_t)(wn * 32 + ((lid >> 4) << 3) + (lid & 7)) * 128;
    const uint32_t b_kincr   = (uint32_t)((lid >> 3) & 1) * 16;

    const int xr_ = t >> 4;           // row 0..15 (stride 16)
    const int xj_ = t & 15;           // float4 col within 64-elem plane

    issue_w_main(sb, 0, t, 0); CP_COMMIT();

    for (int c = 0; c < NCH; ++c) {
        const int k0 = c * KC;
        __syncthreads();
#pragma unroll
        for (int p = 0; p < 2; ++p) {
#pragma unroll
            for (int i = 0; i < 8; ++i) {
                int r = xr_ + (i << 4);
                float4 v = *(const float4*)(xp + (size_t)r * D_DIM + k0 + (p << 6) + (xj_ << 2));
                uint32_t sw = sw128((r << 7) + (xj_ << 3));
                *(uint2*)(smem + XP_OFF(p) + sw) =
                    make_uint2(pkh(__float2half(v.x), __float2half(v.y)),
                               pkh(__float2half(v.z), __float2half(v.w)));
            }
        }
        if (c < NCH - 1) { issue_w_main(sb, (c + 1) & 1, t, (c + 1) * KC); CP_COMMIT(); CP_WAIT1(); }
        else             { CP_WAIT0(); }
        __syncthreads();

#pragma unroll
        for (int kss = 0; kss < 8; ++kss) {
            const int p = kss >> 2;
            const int ks = kss & 3;
            const uint32_t wb = sb + WM_OFF(c & 1, p);
            const uint32_t xb = sb + XP_OFF(p);
            const uint32_t boff = (uint32_t)(ks * 32 + b_kincr) ^ xmask;
            uint32_t bH[8];
            LDSM4(&bH[0], wb + b_rowbase + boff);
            LDSM4(&bH[4], wb + b_rowbase + 2048 + boff);
            const uint32_t aoff = (uint32_t)(ks * 32 + a_kincr) ^ xmask;
#pragma unroll
            for (int mt = 0; mt < 4; ++mt) {
                uint32_t aH[4];
                LDSM4(aH, xb + a_rowbase + mt * 2048 + aoff);
#pragma unroll
                for (int nt = 0; nt < 4; ++nt) {
                    int bi = (nt >> 1) * 4 + (nt & 1) * 2;
                    mma16816(acc[mt][nt], aH, bH[bi], bH[bi + 1]);
                }
            }
        }
    }

    // ================= epilogue =================
    __syncthreads();
    float* lg   = (float*)(smem + LG_OFF);
    float* nsrs = (float*)(smem + NS_OFF);

#pragma unroll
    for (int i = 0; i < 32; i++) {
        int idx = t + (i << 8);
        nsrs[(idx >> 6) * 65 + (idx & 63)] = noise[(size_t)row0 * E_EXP + idx];
    }
#pragma unroll
    for (int mt = 0; mt < 4; ++mt) {
        int r = wm * 64 + mt * 16 + (lid >> 2);
#pragma unroll
        for (int nt = 0; nt < 4; ++nt) {
            int c0 = wn * 32 + nt * 8 + (lid & 3) * 2;
            lg[r * 129 + c0]           = acc[mt][nt][0];
            lg[r * 129 + c0 + 1]       = acc[mt][nt][1];
            lg[(r + 8) * 129 + c0]     = acc[mt][nt][2];
            lg[(r + 8) * 129 + c0 + 1] = acc[mt][nt][3];
        }
    }
    __syncthreads();

    double ps_d = 0.0, sq_d = 0.0;
    if (t < TM) {
        const int r = t;
        float v8, v9;
        row_gate(lg + r * 129, nsrs + r * 65, nsrs + r * 65, &v8, &v9);
        float m = -INFINITY;
        for (int e = 0; e < E_EXP; ++e) m = fmaxf(m, lg[r * 129 + e]);
        float s = 0.f;
        for (int e = 0; e < E_EXP; ++e) s += __expf(lg[r * 129 + e] - m);
        float inv = 1.f / s;
        float ps = 0.f, sq = 0.f;
        for (int e = 0; e < E_EXP; ++e) {
            float p = __expf(lg[r * 129 + e] - m) * inv;
            ps += p; sq += p * p;
        }
        ps_d = ps; sq_d = sq;
        if (v8 - v9 < GAP_THETA) {
            int i = atomicAdd(&g_nflag, 1);
            if (i < CAPROWS) g_flagrows[i] = row0 + r;
        }
    }

    __shared__ double wps[4], wsq[4];
#pragma unroll
    for (int o = 16; o > 0; o >>= 1) {
        ps_d += __shfl_down_sync(0xffffffffu, ps_d, o);
        sq_d += __shfl_down_sync(0xffffffffu, sq_d, o);
    }
    if (wid < 4 && lid == 0) { wps[wid] = ps_d; wsq[wid] = sq_d; }
    __syncthreads();
    if (t == 0) {
        g_ps[blockIdx.x] = wps[0] + wps[1] + wps[2] + wps[3];
        g_sq[blockIdx.x] = wsq[0] + wsq[1] + wsq[2] + wsq[3];
    }
#pragma unroll
    for (int i = 0; i < 32; i++) {
        int idx = t + (i << 8);
        size_t o = (size_t)row0 * E_EXP + idx;
        if (o < (size_t)out_elems) out[o] = nsrs[(idx >> 6) * 65 + (idx & 63)];
    }
}

// ---- Phase A: split-K 4-product repair GEMM ----
__global__ __launch_bounds__(256, 2)
void repair_gemm_kernel(const float* __restrict__ x)
{
    extern __shared__ char smem[];
    const uint32_t sb = smem_u32(smem);
    const int t   = threadIdx.x;
    const int wid = t >> 5;
    const int lid = t & 31;
    const int wm  = wid & 1;
    const int wn  = wid >> 1;

    const int nf = min(g_nflag, CAPROWS);
    const int ntiles = (nf + TM - 1) / TM;
    const int nitems = ntiles * SPLITK;

    __shared__ int ridx[TM];

    const uint32_t xmask     = (uint32_t)(lid & 7) << 4;
    const uint32_t a_rowbase = (uint32_t)(wm * 64 + ((lid >> 3) & 1) * 8 + (lid & 7)) * 128;
    const uint32_t a_kincr   = (uint32_t)(lid >> 4) * 16;
    const uint32_t b_rowbase = (uint32_t)(wn * 32 + ((lid >> 4) << 3) + (lid & 7)) * 128;
    const uint32_t b_kincr   = (uint32_t)((lid >> 3) & 1) * 16;
    const int xr_ = t >> 4;
    const int xj_ = t & 15;

    for (int item = blockIdx.x; item < nitems; item += gridDim.x) {
        const int tile  = item >> 4;
        const int slice = item & (SPLITK - 1);
        const int kbase = slice * KPS * KCR;

        __syncthreads();
        if (t < TM) {
            int gi = tile * TM + t;
            ridx[t] = g_flagrows[gi < nf ? gi : nf - 1];
        }
        issue_w_rep(sb + WBR_OFF(0), t, kbase); CP_COMMIT();
        __syncthreads();

        float acc[4][4][4];
#pragma unroll
        for (int a = 0; a < 4; a++)
#pragma unroll
            for (int b = 0; b < 4; b++)
#pragma unroll
                for (int c = 0; c < 4; c++) acc[a][b][c] = 0.f;

        for (int j = 0; j < KPS; ++j) {
            const int k0 = kbase + j * KCR;
            if (j) __syncthreads();
#pragma unroll
            for (int i = 0; i < 8; ++i) {
                int r = xr_ + (i << 4);
                float4 v = *(const float4*)(x + (size_t)ridx[r] * D_DIM + k0 + (xj_ << 2));
                __half h0 = __float2half(v.x), h1 = __float2half(v.y);
                __half h2 = __float2half(v.z), h3 = __float2half(v.w);
                __half l0 = __float2half(v.x - __half2float(h0)), l1 = __float2half(v.y - __half2float(h1));
                __half l2 = __float2half(v.z - __half2float(h2)), l3 = __float2half(v.w - __half2float(h3));
                uint32_t sw = sw128((r << 7) + (xj_ << 3));
                *(uint2*)(smem + 0      + sw) = make_uint2(pkh(h0, h1), pkh(h2, h3));
                *(uint2*)(smem + XL_OFF + sw) = make_uint2(pkh(l0, l1), pkh(l2, l3));
            }
            if (j < KPS - 1) { issue_w_rep(sb + WBR_OFF((j + 1) & 1), t, k0 + KCR); CP_COMMIT(); CP_WAIT1(); }
            else             { CP_WAIT0(); }
            __syncthreads();

            const uint32_t wb = sb + WBR_OFF(j & 1);
#pragma unroll
            for (int ks = 0; ks < 4; ++ks) {
                const uint32_t boff = (uint32_t)(ks * 32 + b_kincr) ^ xmask;
                uint32_t bH[8], bL[8];
                LDSM4(&bH[0], wb + b_rowbase + boff);
                LDSM4(&bH[4], wb + b_rowbase + 2048 + boff);
                LDSM4(&bL[0], wb + 16384 + b_rowbase + boff);
                LDSM4(&bL[4], wb + 16384 + b_rowbase + 2048 + boff);
                const uint32_t aoff = (uint32_t)(ks * 32 + a_kincr) ^ xmask;
#pragma unroll
                for (int mt = 0; mt < 4; ++mt) {
                    uint32_t aH[4], aL[4];
                    LDSM4(aH, sb + 0      + a_rowbase + mt * 2048 + aoff);
                    LDSM4(aL, sb + XL_OFF + a_rowbase + mt * 2048 + aoff);
#pragma unroll
                    for (int nt = 0; nt < 4; ++nt) {
                        int bi = (nt >> 1) * 4 + (nt & 1) * 2;
                        mma16816(acc[mt][nt], aH, bH[bi], bH[bi + 1]);
                        mma16816(acc[mt][nt], aH, bL[bi], bL[bi + 1]);
                        mma16816(acc[mt][nt], aL, bH[bi], bH[bi + 1]);
                        mma16816(acc[mt][nt], aL, bL[bi], bL[bi + 1]);
                    }
                }
            }
        }

        float* dst = g_scratch + ((size_t)slice * MAXTILES + tile) * (TM * NCOL);
#pragma unroll
        for (int mt = 0; mt < 4; ++mt) {
            int r = wm * 64 + mt * 16 + (lid >> 2);
#pragma unroll
            for (int nt = 0; nt < 4; ++nt) {
                int c0 = wn * 32 + nt * 8 + (lid & 3) * 2;
                dst[r * NCOL + c0]           = acc[mt][nt][0];
                dst[r * NCOL + c0 + 1]       = acc[mt][nt][1];
                dst[(r + 8) * NCOL + c0]     = acc[mt][nt][2];
                dst[(r + 8) * NCOL + c0 + 1] = acc[mt][nt][3];
            }
        }
    }
}

// ---- Phase B: parallel slice-sum + row_gate + scatter; block 0 also finalizes ----
__global__ __launch_bounds__(256, 2)
void repair_fix_kernel(const float* __restrict__ noise, float* __restrict__ out, int out_elems)
{
    __shared__ float lg[FIXROWS * 129];
    __shared__ float ns[FIXROWS * 65];
    const int t = threadIdx.x;
    const int nf = min(g_nflag, CAPROWS);
    const int ntiles = (nf + TM - 1) / TM;
    const int nitems = ntiles * FIXSUB;

    for (int item = blockIdx.x; item < nitems; item += gridDim.x) {
        const int tile  = item >> 4;
        const int rbase = (item & (FIXSUB - 1)) * FIXROWS;
        __syncthreads();
        // sum FIXROWSx128 over 16 slices (fixed order -> deterministic)
        for (int idx = t; idx < FIXROWS * NCOL; idx += 256) {
            int r = idx >> 7, c = idx & 127;
            const float* src = g_scratch + (size_t)tile * (TM * NCOL) + (rbase + r) * NCOL + c;
            float s = 0.f;
#pragma unroll
            for (int sl = 0; sl < SPLITK; ++sl)
                s += src[(size_t)sl * MAXTILES * TM * NCOL];
            lg[r * 129 + c] = s;
        }
        if (t < FIXROWS) {
            int gi = tile * TM + rbase + t;
            if (gi < nf) {
                const float* nrow = noise + (size_t)g_flagrows[gi] * E_EXP;
                for (int e = 0; e < E_EXP; ++e) ns[t * 65 + e] = nrow[e];
            }
        }
        __syncthreads();
        if (t < FIXROWS) {
            int gi = tile * TM + rbase + t;
            if (gi < nf) {
                float v8, v9;
                row_gate(lg + t * 129, ns + t * 65, ns + t * 65, &v8, &v9);
                float* orow = out + (size_t)g_flagrows[gi] * E_EXP;
                for (int e = 0; e < E_EXP; ++e) orow[e] = ns[t * 65 + e];
            }
        }
    }

    // ---- folded finalize (block 0 only; depends only on main-kernel g_ps/g_sq) ----
    if (blockIdx.x == 0) {
        __shared__ double ssum[256], ssq[256];
        double a = 0.0, b = 0.0;
        for (int i = t; i < NBLK; i += 256) { a += g_ps[i]; b += g_sq[i]; }
        ssum[t] = a; ssq[t] = b;
        __syncthreads();
        for (int s = 128; s > 0; s >>= 1) {
            if (t < s) { ssum[t] += ssum[t + s]; ssq[t] += ssq[t + s]; }
            __syncthreads();
        }
        if (t == 0) {
            double n    = (double)B_TOK * (double)E_EXP;
            double mean = ssum[0] / n;
            double var  = (ssq[0] - n * mean * mean) / (n - 1.0);
            float loss  = (float)(var / (mean * mean + 1e-10));
            long long base = (long long)B_TOK * E_EXP;
            if (out_elems == 1) out[0] = loss;
            else for (long long i = base; i < (long long)out_elems; i++) out[i] = loss;
        }
    }
}

extern "C" void kernel_launch(void* const* d_in, const int* in_sizes, int n_in,
                              void* d_out, int out_size)
{
    const float* x  = (const float*)d_in[0];
    const float* wg = (const float*)d_in[1];
    const float* wn = (const float*)d_in[2];
    const float* nz = (const float*)d_in[3];
    float* out = (float*)d_out;

    cudaFuncSetAttribute(gate_mma_kernel,    cudaFuncAttributeMaxDynamicSharedMemorySize, SMEM_BYTES);
    cudaFuncSetAttribute(repair_gemm_kernel, cudaFuncAttributeMaxDynamicSharedMemorySize, SMEM_BYTES);

    wconv_kernel<<<(D_DIM * E_EXP + 255) / 256, 256>>>(wg, wn);
    gate_mma_kernel<<<NBLK, 256, SMEM_BYTES>>>(x, nz, out, out_size);
    repair_gemm_kernel<<<NBLK, 256, SMEM_BYTES>>>(x);
    repair_fix_kernel<<<NBLK, 256>>>(nz, out, out_size);
}